// round 3
// baseline (speedup 1.0000x reference)
#include <cuda_runtime.h>
#include <cstdint>

#define NN 30000
#define DMAXX 16

// ---------------- scratch (static device arrays; no cudaMalloc) -------------
__device__ __align__(16) float d_G1[(size_t)NN * 512];    // feat @ Wih1^T + bih1 + bhh1
__device__ __align__(16) float d_G2[(size_t)NN * 1024];   // X1 @ Wih2^T + bih2 + bhh2
__device__ __align__(16) float d_H1a[(size_t)NN * 128];   // LSTM hidden double buffers (perm order)
__device__ __align__(16) float d_H1b[(size_t)NN * 128];
__device__ __align__(16) float d_C1[(size_t)NN * 128];
__device__ __align__(16) float d_H2a[(size_t)NN * 256];
__device__ __align__(16) float d_H2b[(size_t)NN * 256];
__device__ __align__(16) float d_C2[(size_t)NN * 256];
__device__ __align__(16) float d_M1[(size_t)NN * 128];    // aggregated neighbor hidden, natural order
__device__ __align__(16) float d_M2[(size_t)NN * 256];
__device__ __align__(16) float d_X1[(size_t)NN * 256];    // layer-1 output (post relu)
__device__ int d_perm[NN];
__device__ int d_hist[17];
__device__ int d_suffix[18];   // d_suffix[t+1] = #nodes with deg > t
__device__ int d_offset[17];

// ---------------- degree counting sort (descending) -------------------------
__global__ void k_hist_zero() { if (threadIdx.x < 17) d_hist[threadIdx.x] = 0; }
__global__ void k_hist(const int* __restrict__ deg) {
    int n = blockIdx.x * blockDim.x + threadIdx.x;
    if (n < NN) atomicAdd(&d_hist[deg[n]], 1);
}
__global__ void k_scan() {
    d_suffix[17] = 0;
    for (int dd = 16; dd >= 1; --dd) d_suffix[dd] = d_suffix[dd + 1] + d_hist[dd];
    d_suffix[0] = d_suffix[1];
    for (int dd = 1; dd <= 16; ++dd) d_offset[dd] = d_suffix[dd + 1];
}
__global__ void k_scatter(const int* __restrict__ deg) {
    int n = blockIdx.x * blockDim.x + threadIdx.x;
    if (n < NN) {
        int pos = atomicAdd(&d_offset[deg[n]], 1);
        d_perm[pos] = n;
    }
}

// ---------------- zero-init --------------------------------------------------
__global__ void k_zero_l1() {
    int i = blockIdx.x * blockDim.x + threadIdx.x;
    if (i < NN * 32) {
        ((float4*)d_H1a)[i] = make_float4(0.f, 0.f, 0.f, 0.f);
        ((float4*)d_C1)[i] = make_float4(0.f, 0.f, 0.f, 0.f);
    }
}
__global__ void k_zero_l2() {
    int i = blockIdx.x * blockDim.x + threadIdx.x;
    if (i < NN * 64) {
        ((float4*)d_H2a)[i] = make_float4(0.f, 0.f, 0.f, 0.f);
        ((float4*)d_C2)[i] = make_float4(0.f, 0.f, 0.f, 0.f);
    }
}

// ---------------- tf32 helpers ----------------------------------------------
__device__ __forceinline__ uint32_t f2tf32(float x) {
    uint32_t y;
    asm("cvt.rna.tf32.f32 %0, %1;" : "=r"(y) : "f"(x));
    return y;
}
__device__ __forceinline__ void mma_tf32(float& c0, float& c1, float& c2, float& c3,
                                         uint32_t a0, uint32_t a1, uint32_t a2, uint32_t a3,
                                         uint32_t b0, uint32_t b1) {
    asm volatile(
        "mma.sync.aligned.m16n8k8.row.col.f32.tf32.tf32.f32 "
        "{%0,%1,%2,%3}, {%4,%5,%6,%7}, {%8,%9}, {%0,%1,%2,%3};"
        : "+f"(c0), "+f"(c1), "+f"(c2), "+f"(c3)
        : "r"(a0), "r"(a1), "r"(a2), "r"(a3), "r"(b0), "r"(b1));
}

// ---------------- fragment-major tf32 mainloop -------------------------------
// C[BM,BN] += A[rows,K] @ Wrow-mapped B, BK=32.
// A-frag smem:  As[((k8*(BM/16)+m16)*32 + grp*4+tg)*4 + (half+2*kh)]  -> LDS.128 reads
// B-frag smem:  Bs[((k8*(BN/8)+n8)*32 + grp*4+tg)*2 + kh]            -> LDS.64 reads
template<int BM, int BN, int WARPS_M, int WARPS_N, bool GATED>
__device__ __forceinline__ void mainloop_tf32(
    const float* __restrict__ A, const float* __restrict__ W,
    int K, int rows, int rowBase, int colBase, int Hg,
    uint32_t* As, uint32_t* Bs,
    float acc[(BM / WARPS_M) / 16][(BN / WARPS_N) / 8][4])
{
    constexpr int BK = 32;
    constexpr int MT = (BM / WARPS_M) / 16;
    constexpr int NTT = (BN / WARPS_N) / 8;
    constexpr int NTHR = WARPS_M * WARPS_N * 32;
    const int tid = threadIdx.x;
    const int wid = tid >> 5, lane = tid & 31;
    const int wm = wid / WARPS_N, wn = wid % WARPS_N;

    for (int k0 = 0; k0 < K; k0 += BK) {
#pragma unroll
        for (int idx = tid; idx < BM * (BK / 4); idx += NTHR) {
            int r = idx >> 3;
            int c4 = (idx & 7) << 2;
            int gr = rowBase + r;
            float4 v = make_float4(0.f, 0.f, 0.f, 0.f);
            if (gr < rows) v = *(const float4*)&A[(size_t)gr * K + k0 + c4];
            int m16 = r >> 4, rr = r & 15, half = rr >> 3, grp = rr & 7;
            int k8 = c4 >> 3, kh = (c4 & 7) >> 2;
            uint32_t* dst = &As[((k8 * (BM / 16) + m16) * 32 + grp * 4) * 4 + half + 2 * kh];
            dst[0]  = f2tf32(v.x);
            dst[4]  = f2tf32(v.y);
            dst[8]  = f2tf32(v.z);
            dst[12] = f2tf32(v.w);
        }
#pragma unroll
        for (int idx = tid; idx < BN * (BK / 4); idx += NTHR) {
            int n = idx >> 3;
            int c4 = (idx & 7) << 2;
            int wr = GATED ? ((n >> 5) * Hg + colBase + (n & 31)) : (colBase + n);
            float4 v = *(const float4*)&W[(size_t)wr * K + k0 + c4];
            int n8 = n >> 3, grp = n & 7;
            int k8 = c4 >> 3, kh = (c4 & 7) >> 2;
            uint32_t* dst = &Bs[((k8 * (BN / 8) + n8) * 32 + grp * 4) * 2 + kh];
            dst[0] = f2tf32(v.x);
            dst[2] = f2tf32(v.y);
            dst[4] = f2tf32(v.z);
            dst[6] = f2tf32(v.w);
        }
        __syncthreads();
#pragma unroll
        for (int k8 = 0; k8 < BK / 8; k8++) {
            uint32_t af[MT][4];
            uint32_t bf[NTT][2];
#pragma unroll
            for (int i = 0; i < MT; i++) {
                uint4 tv = *(const uint4*)&As[((k8 * (BM / 16) + wm * MT + i) * 32 + lane) * 4];
                af[i][0] = tv.x; af[i][1] = tv.y; af[i][2] = tv.z; af[i][3] = tv.w;
            }
#pragma unroll
            for (int j = 0; j < NTT; j++) {
                uint2 tv = *(const uint2*)&Bs[((k8 * (BN / 8) + wn * NTT + j) * 32 + lane) * 2];
                bf[j][0] = tv.x; bf[j][1] = tv.y;
            }
#pragma unroll
            for (int i = 0; i < MT; i++)
#pragma unroll
                for (int j = 0; j < NTT; j++)
                    mma_tf32(acc[i][j][0], acc[i][j][1], acc[i][j][2], acc[i][j][3],
                             af[i][0], af[i][1], af[i][2], af[i][3], bf[j][0], bf[j][1]);
        }
        __syncthreads();
    }
}

// ---------------- plain GEMM: C = A @ W^T (+bias0+bias1) (+=C) (relu) --------
template<int BM, int BN, int WARPS_M, int WARPS_N, bool ACC, bool RELU>
__global__ __launch_bounds__(256)
void tgemm_nt(const float* __restrict__ A, const float* __restrict__ W,
              const float* __restrict__ bias0, const float* __restrict__ bias1,
              float* __restrict__ C, int M, int Nn, int K) {
    constexpr int MT = (BM / WARPS_M) / 16;
    constexpr int NTT = (BN / WARPS_N) / 8;
    __shared__ uint32_t As[BM * 32];
    __shared__ uint32_t Bs[BN * 32];

    int rowBase = blockIdx.y * BM;
    int colBase = blockIdx.x * BN;

    float acc[MT][NTT][4];
#pragma unroll
    for (int i = 0; i < MT; i++)
#pragma unroll
        for (int j = 0; j < NTT; j++) {
            acc[i][j][0] = 0.f; acc[i][j][1] = 0.f; acc[i][j][2] = 0.f; acc[i][j][3] = 0.f;
        }

    mainloop_tf32<BM, BN, WARPS_M, WARPS_N, false>(A, W, K, M, rowBase, colBase, 0, As, Bs, acc);

    int wid = threadIdx.x >> 5, lane = threadIdx.x & 31;
    int wm = wid / WARPS_N, wn = wid % WARPS_N;
    int grp = lane >> 2, tg = lane & 3;
    constexpr int WM = BM / WARPS_M;
    constexpr int WN = BN / WARPS_N;

#pragma unroll
    for (int i = 0; i < MT; i++) {
#pragma unroll
        for (int j = 0; j < NTT; j++) {
            int gc = colBase + wn * WN + j * 8 + 2 * tg;
            float b0v = 0.f, b1v = 0.f;
            if (bias0) { b0v += bias0[gc]; b1v += bias0[gc + 1]; }
            if (bias1) { b0v += bias1[gc]; b1v += bias1[gc + 1]; }
            int gr0 = rowBase + wm * WM + i * 16 + grp;
            if (gr0 < M) {
                float v0 = acc[i][j][0] + b0v, v1 = acc[i][j][1] + b1v;
                float* p = &C[(size_t)gr0 * Nn + gc];
                if (ACC) { v0 += p[0]; v1 += p[1]; }
                if (RELU) { v0 = fmaxf(v0, 0.f); v1 = fmaxf(v1, 0.f); }
                *(float2*)p = make_float2(v0, v1);
            }
            int gr1 = gr0 + 8;
            if (gr1 < M) {
                float v0 = acc[i][j][2] + b0v, v1 = acc[i][j][3] + b1v;
                float* p = &C[(size_t)gr1 * Nn + gc];
                if (ACC) { v0 += p[0]; v1 += p[1]; }
                if (RELU) { v0 = fmaxf(v0, 0.f); v1 = fmaxf(v1, 0.f); }
                *(float2*)p = make_float2(v0, v1);
            }
        }
    }
}

// ---------------- fused recurrent LSTM step ----------------------------------
__device__ __forceinline__ float sigm_(float x) { return 1.f / (1.f + __expf(-x)); }

// One step: gates = Hin @ Whh^T (gate-grouped cols) + gathered G row; update C, Hout.
// CTA tile: 128 nodes x 32 hidden units (x 4 gates). 8 warps (2x4).
template<int H>
__global__ __launch_bounds__(256)
void lstm_fused_step(const float* __restrict__ Whh, const float* __restrict__ G,
                     const float* __restrict__ Hin, float* __restrict__ Hout,
                     float* __restrict__ Cst, const int* __restrict__ nbr, int t) {
    __shared__ union SU {
        struct { uint32_t As[128 * 32]; uint32_t Bs[128 * 32]; } mm;
        float stage[64 * 132];
    } su;

    int rows = d_suffix[t + 1];
    int rowBase = blockIdx.y * 128;
    if (rowBase >= rows) return;
    const int cb = blockIdx.x * 32;

    float acc[4][4][4];
#pragma unroll
    for (int i = 0; i < 4; i++)
#pragma unroll
        for (int j = 0; j < 4; j++) {
            acc[i][j][0] = 0.f; acc[i][j][1] = 0.f; acc[i][j][2] = 0.f; acc[i][j][3] = 0.f;
        }

    mainloop_tf32<128, 128, 2, 4, true>(Hin, Whh, H, rows, rowBase, cb, H, su.mm.As, su.mm.Bs, acc);

    int tid = threadIdx.x;
    int wid = tid >> 5, lane = tid & 31;
    int wm = wid / 4, wn = wid % 4;
    int grp = lane >> 2, tg = lane & 3;

    // stage each 64-row half into smem, then pointwise
#pragma unroll 1
    for (int h = 0; h < 2; h++) {
        if (wm == h) {
#pragma unroll
            for (int i = 0; i < 4; i++)
#pragma unroll
                for (int j = 0; j < 4; j++)
#pragma unroll
                    for (int q = 0; q < 4; q++) {
                        int r = i * 16 + grp + 8 * (q >> 1);
                        int n = wn * 32 + j * 8 + 2 * tg + (q & 1);
                        su.stage[r * 132 + n] = acc[i][j][q];
                    }
        }
        __syncthreads();
#pragma unroll
        for (int it = 0; it < 8; it++) {
            int nl = wid * 8 + it;
            int p = rowBase + h * 64 + nl;
            if (p < rows) {
                int node = d_perm[p];
                int nr = nbr[node * DMAXX + t];
                const float* grow = &G[(size_t)nr * 4 * H + cb + lane];
                float gi = su.stage[nl * 132 + lane]      + grow[0];
                float gf = su.stage[nl * 132 + 32 + lane] + grow[H];
                float gg = su.stage[nl * 132 + 64 + lane] + grow[2 * H];
                float go = su.stage[nl * 132 + 96 + lane] + grow[3 * H];
                size_t off = (size_t)p * H + cb + lane;
                float c = Cst[off];
                c = sigm_(gf) * c + sigm_(gi) * tanhf(gg);
                Cst[off] = c;
                Hout[off] = sigm_(go) * tanhf(c);
            }
        }
        __syncthreads();
    }
}

// ---------------- scatter final hidden (buffer by deg parity) ----------------
__global__ void k_scatter_h1(const int* __restrict__ deg) {
    int idx = blockIdx.x * blockDim.x + threadIdx.x;
    if (idx >= NN * 32) return;
    int p = idx >> 5, lane = idx & 31;
    int node = d_perm[p];
    const float4* src = (deg[node] & 1) ? (const float4*)d_H1b : (const float4*)d_H1a;
    ((float4*)d_M1)[node * 32 + lane] = src[p * 32 + lane];
}
__global__ void k_scatter_h2(const int* __restrict__ deg) {
    int idx = blockIdx.x * blockDim.x + threadIdx.x;
    if (idx >= NN * 64) return;
    int p = idx >> 6, lane = idx & 63;
    int node = d_perm[p];
    const float4* src = (deg[node] & 1) ? (const float4*)d_H2b : (const float4*)d_H2a;
    ((float4*)d_M2)[node * 64 + lane] = src[p * 64 + lane];
}

// ---------------- launch -----------------------------------------------------
extern "C" void kernel_launch(void* const* d_in, const int* in_sizes, int n_in,
                              void* d_out, int out_size) {
    const float* feat    = (const float*)d_in[0];
    const int*   nbr     = (const int*)  d_in[1];
    const int*   deg     = (const int*)  d_in[2];
    const float* Wih1    = (const float*)d_in[3];
    const float* Whh1    = (const float*)d_in[4];
    const float* bih1    = (const float*)d_in[5];
    const float* bhh1    = (const float*)d_in[6];
    const float* Wself1  = (const float*)d_in[7];
    const float* Wneigh1 = (const float*)d_in[8];
    const float* b1      = (const float*)d_in[9];
    const float* Wih2    = (const float*)d_in[10];
    const float* Whh2    = (const float*)d_in[11];
    const float* bih2    = (const float*)d_in[12];
    const float* bhh2    = (const float*)d_in[13];
    const float* Wself2  = (const float*)d_in[14];
    const float* Wneigh2 = (const float*)d_in[15];
    const float* b2      = (const float*)d_in[16];
    float* out = (float*)d_out;

    float *pG1, *pG2, *pH1a, *pH1b, *pC1, *pH2a, *pH2b, *pC2, *pM1, *pM2, *pX1;
    cudaGetSymbolAddress((void**)&pG1, d_G1);
    cudaGetSymbolAddress((void**)&pG2, d_G2);
    cudaGetSymbolAddress((void**)&pH1a, d_H1a);
    cudaGetSymbolAddress((void**)&pH1b, d_H1b);
    cudaGetSymbolAddress((void**)&pC1, d_C1);
    cudaGetSymbolAddress((void**)&pH2a, d_H2a);
    cudaGetSymbolAddress((void**)&pH2b, d_H2b);
    cudaGetSymbolAddress((void**)&pC2, d_C2);
    cudaGetSymbolAddress((void**)&pM1, d_M1);
    cudaGetSymbolAddress((void**)&pM2, d_M2);
    cudaGetSymbolAddress((void**)&pX1, d_X1);

    const int MB = (NN + 127) / 128;  // 235

    k_hist_zero<<<1, 32>>>();
    k_hist<<<(NN + 255) / 256, 256>>>(deg);
    k_scan<<<1, 1>>>();
    k_scatter<<<(NN + 255) / 256, 256>>>(deg);

    // ---------------- layer 1 ----------------
    tgemm_nt<128, 128, 2, 4, false, false><<<dim3(4, MB), 256>>>(
        feat, Wih1, bih1, bhh1, pG1, NN, 512, 128);
    k_zero_l1<<<(NN * 32 + 255) / 256, 256>>>();
    for (int t = 0; t < DMAXX; t++) {
        const float* hin = (t & 1) ? pH1b : pH1a;
        float* hout = (t & 1) ? pH1a : pH1b;
        lstm_fused_step<128><<<dim3(4, MB), 256>>>(Whh1, pG1, hin, hout, pC1, nbr, t);
    }
    k_scatter_h1<<<(NN * 32 + 255) / 256, 256>>>(deg);
    tgemm_nt<128, 128, 2, 4, false, false><<<dim3(2, MB), 256>>>(
        feat, Wself1, b1, nullptr, pX1, NN, 256, 128);
    tgemm_nt<128, 128, 2, 4, true, true><<<dim3(2, MB), 256>>>(
        pM1, Wneigh1, nullptr, nullptr, pX1, NN, 256, 128);

    // ---------------- layer 2 ----------------
    tgemm_nt<128, 128, 2, 4, false, false><<<dim3(8, MB), 256>>>(
        pX1, Wih2, bih2, bhh2, pG2, NN, 1024, 256);
    k_zero_l2<<<(NN * 64 + 255) / 256, 256>>>();
    for (int t = 0; t < DMAXX; t++) {
        const float* hin = (t & 1) ? pH2b : pH2a;
        float* hout = (t & 1) ? pH2a : pH2b;
        lstm_fused_step<256><<<dim3(8, MB), 256>>>(Whh2, pG2, hin, hout, pC2, nbr, t);
    }
    k_scatter_h2<<<(NN * 64 + 255) / 256, 256>>>(deg);
    tgemm_nt<128, 64, 2, 4, false, false><<<dim3(1, MB), 256>>>(
        pX1, Wself2, b2, nullptr, out, NN, 64, 256);
    tgemm_nt<128, 64, 2, 4, true, false><<<dim3(1, MB), 256>>>(
        pM2, Wneigh2, nullptr, nullptr, out, NN, 64, 256);
}

// round 4
// speedup vs baseline: 1.8329x; 1.8329x over previous
#include <cuda_runtime.h>
#include <cstdint>

#define NN 30000
#define DMAXX 16

// ---------------- scratch (static device arrays; no cudaMalloc) -------------
__device__ __align__(16) float d_G1[(size_t)NN * 512];    // feat @ Wih1^T + biases
__device__ __align__(16) float d_GB[(size_t)NN * 1024];   // recurrent gate buffer (shared by both layers)
__device__ __align__(16) float d_H1p[(size_t)NN * 128];   // LSTM state, permuted order
__device__ __align__(16) float d_C1p[(size_t)NN * 128];
__device__ __align__(16) float d_M1[(size_t)NN * 128];    // aggregated neighbor hidden, natural order
__device__ __align__(16) float d_X1[(size_t)NN * 256];    // layer-1 output (post relu)
__device__ __align__(16) float d_G2[(size_t)NN * 1024];   // X1 @ Wih2^T + biases
__device__ __align__(16) float d_H2p[(size_t)NN * 256];
__device__ __align__(16) float d_C2p[(size_t)NN * 256];
__device__ __align__(16) float d_M2[(size_t)NN * 256];
__device__ int d_perm[NN];
__device__ int d_hist[17];
__device__ int d_suffix[18];   // d_suffix[t+1] = #nodes with deg > t
__device__ int d_offset[17];

// ---------------- degree counting sort (descending) -------------------------
__global__ void k_hist_zero() { if (threadIdx.x < 17) d_hist[threadIdx.x] = 0; }
__global__ void k_hist(const int* __restrict__ deg) {
    int n = blockIdx.x * blockDim.x + threadIdx.x;
    if (n < NN) atomicAdd(&d_hist[deg[n]], 1);
}
__global__ void k_scan() {
    d_suffix[17] = 0;
    for (int dd = 16; dd >= 1; --dd) d_suffix[dd] = d_suffix[dd + 1] + d_hist[dd];
    d_suffix[0] = d_suffix[1];
    for (int dd = 1; dd <= 16; ++dd) d_offset[dd] = d_suffix[dd + 1];
}
__global__ void k_scatter(const int* __restrict__ deg) {
    int n = blockIdx.x * blockDim.x + threadIdx.x;
    if (n < NN) {
        int pos = atomicAdd(&d_offset[deg[n]], 1);
        d_perm[pos] = n;
    }
}

// ---------------- zero-init of LSTM states ---------------------------------
__global__ void k_zero_l1() {
    int i = blockIdx.x * blockDim.x + threadIdx.x;
    if (i < NN * 32) {
        ((float4*)d_H1p)[i] = make_float4(0.f, 0.f, 0.f, 0.f);
        ((float4*)d_C1p)[i] = make_float4(0.f, 0.f, 0.f, 0.f);
    }
}
__global__ void k_zero_l2() {
    int i = blockIdx.x * blockDim.x + threadIdx.x;
    if (i < NN * 64) {
        ((float4*)d_H2p)[i] = make_float4(0.f, 0.f, 0.f, 0.f);
        ((float4*)d_C2p)[i] = make_float4(0.f, 0.f, 0.f, 0.f);
    }
}

// ---------------- tf32 helpers ----------------------------------------------
__device__ __forceinline__ uint32_t f2tf32(float x) {
    uint32_t y;
    asm("cvt.rna.tf32.f32 %0, %1;" : "=r"(y) : "f"(x));
    return y;
}
__device__ __forceinline__ void mma_tf32(float& c0, float& c1, float& c2, float& c3,
                                         uint32_t a0, uint32_t a1, uint32_t a2, uint32_t a3,
                                         uint32_t b0, uint32_t b1) {
    asm volatile(
        "mma.sync.aligned.m16n8k8.row.col.f32.tf32.tf32.f32 "
        "{%0,%1,%2,%3}, {%4,%5,%6,%7}, {%8,%9}, {%0,%1,%2,%3};"
        : "+f"(c0), "+f"(c1), "+f"(c2), "+f"(c3)
        : "r"(a0), "r"(a1), "r"(a2), "r"(a3), "r"(b0), "r"(b1));
}

// ---------------- tf32 GEMM, BK=32, register double-buffered -----------------
// C[M,Nn] = A[M,K] @ W[Nn,K]^T (+bias0+bias1) (+=C) (relu). Padded smem LDS_=36:
// fragment loads conflict-free (grp*36+tg covers banks 0..31).
template<int BM, int BN, int WARPS_M, int WARPS_N, bool ACC, bool RELU>
__global__ __launch_bounds__(256)
void tgemm_nt(const float* __restrict__ A, const float* __restrict__ W,
              const float* __restrict__ bias0, const float* __restrict__ bias1,
              float* __restrict__ C, int M, int Nn, int K,
              const int* rowsDev) {
    constexpr int BK = 32;
    constexpr int LDS_ = BK + 4;           // 36
    constexpr int WM = BM / WARPS_M;
    constexpr int WN = BN / WARPS_N;
    constexpr int MT = WM / 16;
    constexpr int NTT = WN / 8;
    constexpr int NTHR = WARPS_M * WARPS_N * 32;
    constexpr int AIT = BM * (BK / 4) / NTHR;   // float4 loads per thread (A)
    constexpr int BIT = BN * (BK / 4) / NTHR;   // float4 loads per thread (B)

    int rows = rowsDev ? *rowsDev : M;
    int rowBase = blockIdx.y * BM;
    if (rowBase >= rows) return;
    int colBase = blockIdx.x * BN;

    __shared__ uint32_t As[BM * LDS_];
    __shared__ uint32_t Bs[BN * LDS_];

    int tid = threadIdx.x;
    int wid = tid >> 5;
    int lane = tid & 31;
    int wm = wid / WARPS_N;
    int wn = wid % WARPS_N;
    int grp = lane >> 2;
    int tg = lane & 3;

    float acc[MT][NTT][4];
#pragma unroll
    for (int i = 0; i < MT; i++)
#pragma unroll
        for (int j = 0; j < NTT; j++) {
            acc[i][j][0] = 0.f; acc[i][j][1] = 0.f; acc[i][j][2] = 0.f; acc[i][j][3] = 0.f;
        }

    float4 ra[AIT], rb[BIT];

    // prefetch first tile into registers
#pragma unroll
    for (int u = 0; u < AIT; u++) {
        int idx = tid + u * NTHR;
        int r = idx / (BK / 4), c4 = (idx % (BK / 4)) * 4;
        int gr = rowBase + r;
        ra[u] = (gr < rows) ? *(const float4*)&A[(size_t)gr * K + c4]
                            : make_float4(0.f, 0.f, 0.f, 0.f);
    }
#pragma unroll
    for (int u = 0; u < BIT; u++) {
        int idx = tid + u * NTHR;
        int r = idx / (BK / 4), c4 = (idx % (BK / 4)) * 4;
        rb[u] = *(const float4*)&W[(size_t)(colBase + r) * K + c4];
    }

    for (int k0 = 0; k0 < K; k0 += BK) {
        // commit current registers to smem (tf32 convert)
#pragma unroll
        for (int u = 0; u < AIT; u++) {
            int idx = tid + u * NTHR;
            int r = idx / (BK / 4), c4 = (idx % (BK / 4)) * 4;
            uint32_t* dst = &As[r * LDS_ + c4];
            dst[0] = f2tf32(ra[u].x); dst[1] = f2tf32(ra[u].y);
            dst[2] = f2tf32(ra[u].z); dst[3] = f2tf32(ra[u].w);
        }
#pragma unroll
        for (int u = 0; u < BIT; u++) {
            int idx = tid + u * NTHR;
            int r = idx / (BK / 4), c4 = (idx % (BK / 4)) * 4;
            uint32_t* dst = &Bs[r * LDS_ + c4];
            dst[0] = f2tf32(rb[u].x); dst[1] = f2tf32(rb[u].y);
            dst[2] = f2tf32(rb[u].z); dst[3] = f2tf32(rb[u].w);
        }
        __syncthreads();

        // prefetch next tile (overlaps with MMA below)
        int kn = k0 + BK;
        if (kn < K) {
#pragma unroll
            for (int u = 0; u < AIT; u++) {
                int idx = tid + u * NTHR;
                int r = idx / (BK / 4), c4 = (idx % (BK / 4)) * 4;
                int gr = rowBase + r;
                ra[u] = (gr < rows) ? *(const float4*)&A[(size_t)gr * K + kn + c4]
                                    : make_float4(0.f, 0.f, 0.f, 0.f);
            }
#pragma unroll
            for (int u = 0; u < BIT; u++) {
                int idx = tid + u * NTHR;
                int r = idx / (BK / 4), c4 = (idx % (BK / 4)) * 4;
                rb[u] = *(const float4*)&W[(size_t)(colBase + r) * K + kn + c4];
            }
        }

#pragma unroll
        for (int kk = 0; kk < BK; kk += 8) {
            uint32_t af[MT][4];
#pragma unroll
            for (int i = 0; i < MT; i++) {
                int r0 = wm * WM + i * 16 + grp;
                int c = kk + tg;
                af[i][0] = As[r0 * LDS_ + c];
                af[i][1] = As[(r0 + 8) * LDS_ + c];
                af[i][2] = As[r0 * LDS_ + c + 4];
                af[i][3] = As[(r0 + 8) * LDS_ + c + 4];
            }
            uint32_t bf[NTT][2];
#pragma unroll
            for (int j = 0; j < NTT; j++) {
                int n0 = wn * WN + j * 8 + grp;
                bf[j][0] = Bs[n0 * LDS_ + kk + tg];
                bf[j][1] = Bs[n0 * LDS_ + kk + tg + 4];
            }
#pragma unroll
            for (int i = 0; i < MT; i++)
#pragma unroll
                for (int j = 0; j < NTT; j++)
                    mma_tf32(acc[i][j][0], acc[i][j][1], acc[i][j][2], acc[i][j][3],
                             af[i][0], af[i][1], af[i][2], af[i][3], bf[j][0], bf[j][1]);
        }
        __syncthreads();
    }

    // epilogue
#pragma unroll
    for (int i = 0; i < MT; i++) {
#pragma unroll
        for (int j = 0; j < NTT; j++) {
            int gc = colBase + wn * WN + j * 8 + 2 * tg;
            float b0v = 0.f, b1v = 0.f;
            if (bias0) { b0v += bias0[gc]; b1v += bias0[gc + 1]; }
            if (bias1) { b0v += bias1[gc]; b1v += bias1[gc + 1]; }
            int gr0 = rowBase + wm * WM + i * 16 + grp;
            if (gr0 < rows) {
                float v0 = acc[i][j][0] + b0v, v1 = acc[i][j][1] + b1v;
                float* p = &C[(size_t)gr0 * Nn + gc];
                if (ACC) { v0 += p[0]; v1 += p[1]; }
                if (RELU) { v0 = fmaxf(v0, 0.f); v1 = fmaxf(v1, 0.f); }
                *(float2*)p = make_float2(v0, v1);
            }
            int gr1 = gr0 + 8;
            if (gr1 < rows) {
                float v0 = acc[i][j][2] + b0v, v1 = acc[i][j][3] + b1v;
                float* p = &C[(size_t)gr1 * Nn + gc];
                if (ACC) { v0 += p[0]; v1 += p[1]; }
                if (RELU) { v0 = fmaxf(v0, 0.f); v1 = fmaxf(v1, 0.f); }
                *(float2*)p = make_float2(v0, v1);
            }
        }
    }
}

// ---------------- LSTM pointwise steps --------------------------------------
__device__ __forceinline__ float sigm_(float x) { return 1.f / (1.f + __expf(-x)); }

// layer 1: H=128; 32 threads/node, each thread does 4 hidden units
__global__ void lstm_step1(const int* __restrict__ nbr, int t) {
    int cnt = d_suffix[t + 1];
    int idx = blockIdx.x * blockDim.x + threadIdx.x;
    int p = idx >> 5;
    if (p >= cnt) return;
    int lane = idx & 31;
    int node = d_perm[p];
    int nr = nbr[node * DMAXX + t];
    const float4* gb = (const float4*)&d_GB[(size_t)p * 512];
    const float4* gx = (const float4*)&d_G1[(size_t)nr * 512];
    float4 gi = gb[lane],       xi = gx[lane];
    float4 gf = gb[32 + lane],  xf = gx[32 + lane];
    float4 gg = gb[64 + lane],  xg = gx[64 + lane];
    float4 go = gb[96 + lane],  xo = gx[96 + lane];
    float4* cp = (float4*)&d_C1p[(size_t)p * 128];
    float4* hp = (float4*)&d_H1p[(size_t)p * 128];
    float4 c = cp[lane];
    float4 h;
    c.x = sigm_(gf.x + xf.x) * c.x + sigm_(gi.x + xi.x) * tanhf(gg.x + xg.x); h.x = sigm_(go.x + xo.x) * tanhf(c.x);
    c.y = sigm_(gf.y + xf.y) * c.y + sigm_(gi.y + xi.y) * tanhf(gg.y + xg.y); h.y = sigm_(go.y + xo.y) * tanhf(c.y);
    c.z = sigm_(gf.z + xf.z) * c.z + sigm_(gi.z + xi.z) * tanhf(gg.z + xg.z); h.z = sigm_(go.z + xo.z) * tanhf(c.z);
    c.w = sigm_(gf.w + xf.w) * c.w + sigm_(gi.w + xi.w) * tanhf(gg.w + xg.w); h.w = sigm_(go.w + xo.w) * tanhf(c.w);
    cp[lane] = c; hp[lane] = h;
}

// layer 2: H=256; 64 threads/node
__global__ void lstm_step2(const int* __restrict__ nbr, int t) {
    int cnt = d_suffix[t + 1];
    int idx = blockIdx.x * blockDim.x + threadIdx.x;
    int p = idx >> 6;
    if (p >= cnt) return;
    int lane = idx & 63;
    int node = d_perm[p];
    int nr = nbr[node * DMAXX + t];
    const float4* gb = (const float4*)&d_GB[(size_t)p * 1024];
    const float4* gx = (const float4*)&d_G2[(size_t)nr * 1024];
    float4 gi = gb[lane],        xi = gx[lane];
    float4 gf = gb[64 + lane],   xf = gx[64 + lane];
    float4 gg = gb[128 + lane],  xg = gx[128 + lane];
    float4 go = gb[192 + lane],  xo = gx[192 + lane];
    float4* cp = (float4*)&d_C2p[(size_t)p * 256];
    float4* hp = (float4*)&d_H2p[(size_t)p * 256];
    float4 c = cp[lane];
    float4 h;
    c.x = sigm_(gf.x + xf.x) * c.x + sigm_(gi.x + xi.x) * tanhf(gg.x + xg.x); h.x = sigm_(go.x + xo.x) * tanhf(c.x);
    c.y = sigm_(gf.y + xf.y) * c.y + sigm_(gi.y + xi.y) * tanhf(gg.y + xg.y); h.y = sigm_(go.y + xo.y) * tanhf(c.y);
    c.z = sigm_(gf.z + xf.z) * c.z + sigm_(gi.z + xi.z) * tanhf(gg.z + xg.z); h.z = sigm_(go.z + xo.z) * tanhf(c.z);
    c.w = sigm_(gf.w + xf.w) * c.w + sigm_(gi.w + xi.w) * tanhf(gg.w + xg.w); h.w = sigm_(go.w + xo.w) * tanhf(c.w);
    cp[lane] = c; hp[lane] = h;
}

// scatter permuted final hidden state back to natural node order
__global__ void k_scatter_h1() {
    int idx = blockIdx.x * blockDim.x + threadIdx.x;
    if (idx >= NN * 32) return;
    int p = idx >> 5, lane = idx & 31;
    int node = d_perm[p];
    ((float4*)d_M1)[node * 32 + lane] = ((const float4*)d_H1p)[p * 32 + lane];
}
__global__ void k_scatter_h2() {
    int idx = blockIdx.x * blockDim.x + threadIdx.x;
    if (idx >= NN * 64) return;
    int p = idx >> 6, lane = idx & 63;
    int node = d_perm[p];
    ((float4*)d_M2)[node * 64 + lane] = ((const float4*)d_H2p)[p * 64 + lane];
}

// ---------------- launch -----------------------------------------------------
extern "C" void kernel_launch(void* const* d_in, const int* in_sizes, int n_in,
                              void* d_out, int out_size) {
    const float* feat    = (const float*)d_in[0];
    const int*   nbr     = (const int*)  d_in[1];
    const int*   deg     = (const int*)  d_in[2];
    const float* Wih1    = (const float*)d_in[3];
    const float* Whh1    = (const float*)d_in[4];
    const float* bih1    = (const float*)d_in[5];
    const float* bhh1    = (const float*)d_in[6];
    const float* Wself1  = (const float*)d_in[7];
    const float* Wneigh1 = (const float*)d_in[8];
    const float* b1      = (const float*)d_in[9];
    const float* Wih2    = (const float*)d_in[10];
    const float* Whh2    = (const float*)d_in[11];
    const float* bih2    = (const float*)d_in[12];
    const float* bhh2    = (const float*)d_in[13];
    const float* Wself2  = (const float*)d_in[14];
    const float* Wneigh2 = (const float*)d_in[15];
    const float* b2      = (const float*)d_in[16];
    float* out = (float*)d_out;

    float *pG1, *pGB, *pH1, *pM1, *pX1, *pG2, *pH2, *pM2;
    int* pSuf;
    cudaGetSymbolAddress((void**)&pG1, d_G1);
    cudaGetSymbolAddress((void**)&pGB, d_GB);
    cudaGetSymbolAddress((void**)&pH1, d_H1p);
    cudaGetSymbolAddress((void**)&pM1, d_M1);
    cudaGetSymbolAddress((void**)&pX1, d_X1);
    cudaGetSymbolAddress((void**)&pG2, d_G2);
    cudaGetSymbolAddress((void**)&pH2, d_H2p);
    cudaGetSymbolAddress((void**)&pM2, d_M2);
    cudaGetSymbolAddress((void**)&pSuf, d_suffix);

    const int MB = (NN + 127) / 128;  // 235

    k_hist_zero<<<1, 32>>>();
    k_hist<<<(NN + 255) / 256, 256>>>(deg);
    k_scan<<<1, 1>>>();
    k_scatter<<<(NN + 255) / 256, 256>>>(deg);

    // ---------------- layer 1 ----------------
    tgemm_nt<128, 128, 2, 4, false, false><<<dim3(4, MB), 256>>>(
        feat, Wih1, bih1, bhh1, pG1, NN, 512, 128, nullptr);
    k_zero_l1<<<(NN * 32 + 255) / 256, 256>>>();
    for (int t = 0; t < DMAXX; t++) {
        tgemm_nt<128, 128, 2, 4, false, false><<<dim3(4, MB), 256>>>(
            pH1, Whh1, nullptr, nullptr, pGB, NN, 512, 128, pSuf + (t + 1));
        lstm_step1<<<(NN * 32 + 255) / 256, 256>>>(nbr, t);
    }
    k_scatter_h1<<<(NN * 32 + 255) / 256, 256>>>();
    tgemm_nt<128, 128, 2, 4, false, false><<<dim3(2, MB), 256>>>(
        feat, Wself1, b1, nullptr, pX1, NN, 256, 128, nullptr);
    tgemm_nt<128, 128, 2, 4, true, true><<<dim3(2, MB), 256>>>(
        pM1, Wneigh1, nullptr, nullptr, pX1, NN, 256, 128, nullptr);

    // ---------------- layer 2 ----------------
    tgemm_nt<128, 128, 2, 4, false, false><<<dim3(8, MB), 256>>>(
        pX1, Wih2, bih2, bhh2, pG2, NN, 1024, 256, nullptr);
    k_zero_l2<<<(NN * 64 + 255) / 256, 256>>>();
    for (int t = 0; t < DMAXX; t++) {
        tgemm_nt<128, 128, 2, 4, false, false><<<dim3(8, MB), 256>>>(
            pH2, Whh2, nullptr, nullptr, pGB, NN, 1024, 256, pSuf + (t + 1));
        lstm_step2<<<(NN * 64 + 255) / 256, 256>>>(nbr, t);
    }
    k_scatter_h2<<<(NN * 64 + 255) / 256, 256>>>();
    tgemm_nt<128, 64, 2, 4, false, false><<<dim3(1, MB), 256>>>(
        pX1, Wself2, b2, nullptr, out, NN, 64, 256, nullptr);
    tgemm_nt<128, 64, 2, 4, true, false><<<dim3(1, MB), 256>>>(
        pM2, Wneigh2, nullptr, nullptr, out, NN, 64, 256, nullptr);
}